// round 15
// baseline (speedup 1.0000x reference)
#include <cuda_runtime.h>
#include <math_constants.h>
#include <math.h>

#define BB 32
#define NN 1024
#define FF 10
#define DD 64
#define MM 4
#define RR 8
#define KK 20
#define NROWS (BB*NN)           // 32768
#define BN_EPS 1e-5f
#define HCHUNK 16
#define NSLICE 8                // 1024/128 column slices

typedef unsigned long long ull;

// ---------------- scratch (device globals; no runtime allocation) ----------------
__device__ float g_hit[NROWS*DD];
__device__ float g_xlin[NROWS*DD];
__device__ float g_eit[NROWS];
__device__ float g_hpart[HCHUNK*BB*DD];
__device__ float g_dpart[HCHUNK*BB];
__device__ float g_pih[BB*MM];
__device__ float g_proto[MM*NN*DD];
__device__ float g_mixed[NROWS*DD];
__device__ float g_si[NROWS];
__device__ float g_sj[NROWS];
__device__ float g_cv[NSLICE*KK*NROWS];   // candidates, transposed: [(slice*20+s)][row]
__device__ int   g_ci[NSLICE*KK*NROWS];
__device__ float g_tv[NROWS*KK];
__device__ int   g_ti[NROWS*KK];
__device__ float g_gnn[NROWS*DD];
__device__ double g_stats[4*DD];

// ---------------- helpers ----------------
__device__ __forceinline__ float nanfix(float x){
  if (isnan(x)) return 0.f;
  if (isinf(x)) return x > 0.f ? 1e4f : -1e4f;
  return x;
}
__device__ __forceinline__ float lrelu(float x){ return x >= 0.f ? x : 0.2f*x; }

__device__ __forceinline__ ull ffma2(ull a, ull b, ull c){
  ull d;
  asm("fma.rn.f32x2 %0, %1, %2, %3;" : "=l"(d) : "l"(a), "l"(b), "l"(c));
  return d;
}
__device__ __forceinline__ ull dup2(float a){
  ull r;
  asm("mov.b64 %0, {%1, %1};" : "=l"(r) : "f"(a));
  return r;
}
__device__ __forceinline__ void unpack2(ull v, float& lo, float& hi){
  asm("mov.b64 {%0, %1}, %2;" : "=f"(lo), "=f"(hi) : "l"(v));
}

// min-replace top-20 insert; key order = (val desc, idx asc), matching lax.top_k.
// Evicts the slot with smallest (val, -idx) key.
__device__ __forceinline__ void upd20(float v, int j, float* cv, int* ci,
                                      float& vmin, int& mi, int& mslot){
  if (v > vmin || (v == vmin && j < mi)){
    cv[mslot] = v; ci[mslot] = j;
    vmin = cv[0]; mi = ci[0]; mslot = 0;
    #pragma unroll 1
    for (int s = 1; s < 20; s++){
      float a = cv[s]; int b2 = ci[s];
      if (a < vmin || (a == vmin && b2 > mi)){ vmin = a; mi = b2; mslot = s; }
    }
  }
}

// ---------------- K1: cond MLP (h_it, e_it) + x_lin + proto fold + stats zero ----------------
__global__ void __launch_bounds__(256) k_cond(const float* __restrict__ data,
    const float* __restrict__ Wc, const float* __restrict__ bc,
    const float* __restrict__ Wap, const float* __restrict__ bap,
    const float* __restrict__ Wav, const float* __restrict__ Wg,
    const float* __restrict__ ebase, const float* __restrict__ lru,
    const float* __restrict__ lrv){
  __shared__ float Wap_s[DD*DD];
  __shared__ float Wc_s[FF*DD];
  __shared__ float Wg_s[FF*DD];
  __shared__ float hbuf[8][DD];
  int t = threadIdx.x;
  if (blockIdx.x == 0) g_stats[t] = 0.0;
  for (int e = t; e < DD*DD; e += 256) Wap_s[e] = Wap[e];
  for (int e = t; e < FF*DD; e += 256){ Wc_s[e] = Wc[e]; Wg_s[e] = Wg[e]; }
  int warp = t >> 5, lane = t & 31;
  int row = blockIdx.x*8 + warp;
  if (blockIdx.x < MM*NN/8){
    int rown = blockIdx.x*8 + warp;        // m*NN + n
    int m = rown >> 10, n = rown & (NN-1);
    int pd0 = lane, pd1 = lane + 32;
    float p0 = ebase[n*DD+pd0], p1 = ebase[n*DD+pd1];
    #pragma unroll
    for (int r = 0; r < RR; r++){
      float u = lru[rown*RR + r];
      p0 = fmaf(u, lrv[(m*RR+r)*DD+pd0], p0);
      p1 = fmaf(u, lrv[(m*RR+r)*DD+pd1], p1);
    }
    g_proto[rown*DD+pd0] = p0;
    g_proto[rown*DD+pd1] = p1;
  }
  __syncthreads();
  const float* dr = data + row*FF;
  float x[FF];
  #pragma unroll
  for (int f = 0; f < FF; f++) x[f] = dr[f];
  int d0 = lane, d1 = lane + 32;
  float h0 = bc[d0], h1 = bc[d1], xl0 = 0.f, xl1 = 0.f;
  #pragma unroll
  for (int f = 0; f < FF; f++){
    h0  = fmaf(x[f], Wc_s[f*DD+d0], h0);
    h1  = fmaf(x[f], Wc_s[f*DD+d1], h1);
    xl0 = fmaf(x[f], Wg_s[f*DD+d0], xl0);
    xl1 = fmaf(x[f], Wg_s[f*DD+d1], xl1);
  }
  g_hit[row*DD+d0] = h0;  g_hit[row*DD+d1] = h1;
  g_xlin[row*DD+d0] = xl0; g_xlin[row*DD+d1] = xl1;
  hbuf[warp][d0] = h0; hbuf[warp][d1] = h1;
  __syncwarp();
  float a0 = bap[d0], a1 = bap[d1];
  #pragma unroll 16
  for (int e = 0; e < DD; e++){
    float he = hbuf[warp][e];
    a0 = fmaf(he, Wap_s[e*DD+d0], a0);
    a1 = fmaf(he, Wap_s[e*DD+d1], a1);
  }
  a0 = lrelu(a0); a1 = lrelu(a1);
  float ts = a0*Wav[d0] + a1*Wav[d1];
  #pragma unroll
  for (int off = 16; off > 0; off >>= 1) ts += __shfl_xor_sync(0xffffffffu, ts, off);
  if (lane == 0) g_eit[row] = nanfix(ts);
}

// ---------------- K2: h_sys partial sums + partial denominators (no-max softmax) ----------------
__global__ void __launch_bounds__(256) k_hsys(){
  int chunk = blockIdx.x;            // 0..15 (64 rows each)
  int b = blockIdx.y;
  int t = threadIdx.x;
  int d = t & 63, r4 = t >> 6;
  __shared__ float we[64];
  __shared__ float red[256];
  int n0 = chunk*64;
  const float* e = g_eit + b*NN + n0;
  if (t < 64) we[t] = expf(e[t]);
  __syncthreads();
  const float* h = g_hit + ((size_t)b*NN + n0)*DD;
  float acc = 0.f;
  #pragma unroll 4
  for (int r = r4; r < 64; r += 4)
    acc = fmaf(we[r], h[r*DD + d], acc);
  red[t] = acc; __syncthreads();
  if (t < 64)
    g_hpart[(chunk*BB + b)*DD + d] = red[d] + red[d+64] + red[d+128] + red[d+192];
  if (t >= 64 && t < 96){
    int lane = t - 64;
    float s = we[lane] + we[lane+32];
    #pragma unroll
    for (int off = 16; off > 0; off >>= 1) s += __shfl_xor_sync(0xffffffffu, s, off);
    if (lane == 0) g_dpart[chunk*BB + b] = s;
  }
}

// ---------------- K3: finalize h_sys + gumbel top-2 routing ----------------
__global__ void __launch_bounds__(64) k_route(const float* __restrict__ Wr,
    const float* __restrict__ br, const float* __restrict__ gum,
    float* __restrict__ hs_out, float* __restrict__ ps_out){
  int b = blockIdx.x, t = threadIdx.x;
  __shared__ float shs[DD];
  __shared__ float slog[MM];
  float s = 0.f;
  #pragma unroll
  for (int c = 0; c < HCHUNK; c++) s += g_hpart[(c*BB + b)*DD + t];
  float den = 0.f;
  #pragma unroll
  for (int c = 0; c < HCHUNK; c++) den += g_dpart[c*BB + b];
  float hs = s / den;
  shs[t] = hs;
  hs_out[b*DD + t] = hs;
  __syncthreads();
  if (t < MM){
    float lg = br[t] + gum[b*MM + t];
    #pragma unroll 8
    for (int dd2 = 0; dd2 < DD; dd2++) lg = fmaf(shs[dd2], Wr[dd2*MM + t], lg);
    slog[t] = lg;
  }
  __syncthreads();
  if (t == 0){
    float mm = slog[0];
    #pragma unroll
    for (int i = 1; i < MM; i++) mm = fmaxf(mm, slog[i]);
    float p[MM]; float sp = 0.f;
    #pragma unroll
    for (int i = 0; i < MM; i++){ p[i] = expf(slog[i] - mm); sp += p[i]; }
    #pragma unroll
    for (int i = 0; i < MM; i++){ p[i] /= sp; ps_out[b*MM + i] = p[i]; }
    int i1 = 0;
    #pragma unroll
    for (int i = 1; i < MM; i++) if (p[i] > p[i1]) i1 = i;
    int i2 = -1;
    #pragma unroll
    for (int i = 0; i < MM; i++){
      if (i == i1) continue;
      if (i2 < 0 || p[i] > p[i2]) i2 = i;
    }
    float nrm = fmaxf(p[i1] + p[i2], 1e-12f);
    #pragma unroll
    for (int i = 0; i < MM; i++) g_pih[b*MM + i] = 0.f;
    g_pih[b*MM + i1] = p[i1] / nrm;
    g_pih[b*MM + i2] = p[i2] / nrm;
  }
}

// ---------------- K4: mixed = pi @ proto, + s_i / s_j ----------------
__global__ void __launch_bounds__(256) k_mixed(const float* __restrict__ ai,
    const float* __restrict__ aj, const float* __restrict__ aei,
    const float* __restrict__ aej){
  int t = threadIdx.x, warp = t >> 5, lane = t & 31;
  int row = blockIdx.x*8 + warp;
  int b = row >> 10, n = row & (NN-1);
  int d0 = lane, d1 = lane + 32;
  float pi0 = g_pih[b*MM+0], pi1 = g_pih[b*MM+1];
  float pi2 = g_pih[b*MM+2], pi3 = g_pih[b*MM+3];
  float mx0, mx1;
  {
    const float* p0 = g_proto + (0*NN+n)*DD;
    const float* p1 = g_proto + (1*NN+n)*DD;
    const float* p2 = g_proto + (2*NN+n)*DD;
    const float* p3 = g_proto + (3*NN+n)*DD;
    mx0 = pi0*p0[d0] + pi1*p1[d0] + pi2*p2[d0] + pi3*p3[d0];
    mx1 = pi0*p0[d1] + pi1*p1[d1] + pi2*p2[d1] + pi3*p3[d1];
  }
  mx0 = nanfix(mx0); mx1 = nanfix(mx1);
  g_mixed[row*DD+d0] = mx0;
  g_mixed[row*DD+d1] = mx1;
  float xl0 = g_xlin[row*DD+d0], xl1 = g_xlin[row*DD+d1];
  float r1 = xl0*ai[d0] + mx0*aei[d0] + xl1*ai[d1] + mx1*aei[d1];
  float r2 = xl0*aj[d0] + mx0*aej[d0] + xl1*aj[d1] + mx1*aej[d1];
  #pragma unroll
  for (int off = 16; off > 0; off >>= 1){
    r1 += __shfl_xor_sync(0xffffffffu, r1, off);
    r2 += __shfl_xor_sync(0xffffffffu, r2, off);
  }
  if (lane == 0){ g_si[row] = r1; g_sj[row] = r2; }
}

// ---------------- K5: scores tile + in-block local top-20 (no global scores!) ----------------
// Compute C[128x128] = A·B^T in f32x2 (bit-identical to prior kernels), park the tile in
// smem (reusing the A/B buffers), then 256 threads do per-lane-serial top-20:
// threads 0-127 -> rows of the i-tile (direct read), threads 128-255 -> rows of the
// j-tile (transposed read; skipped on diagonal tiles). 20 candidates per (row, slice)
// written to transposed/coalesced candidate arrays.
__global__ void __launch_bounds__(256, 2) k_scores(){
  extern __shared__ float smem[];
  float* Ast = smem;               // [64][132] during compute
  float* Bst = smem + 64*132;      // [64][132] during compute
  float* sc  = smem;               // [128][132] after compute (aliases Ast+Bst)
  int b = blockIdx.z;
  int p = blockIdx.x, ti = 0;
  while (p >= 8 - ti){ p -= 8 - ti; ti++; }
  int tj = ti + p;
  int bi = ti*128, bj = tj*128;
  int t = threadIdx.x;
  const float* A  = g_mixed + ((size_t)b*NN + bi)*DD;
  const float* Bm = g_mixed + ((size_t)b*NN + bj)*DD;
  {
    int i = t >> 1, kh = (t & 1) * 32;
    const float4* a4 = (const float4*)(A  + i*DD + kh);
    const float4* b4 = (const float4*)(Bm + i*DD + kh);
    #pragma unroll
    for (int q = 0; q < 8; q++){
      float4 av = a4[q], bv = b4[q];
      int k = kh + q*4;
      Ast[(k+0)*132 + i] = av.x; Ast[(k+1)*132 + i] = av.y;
      Ast[(k+2)*132 + i] = av.z; Ast[(k+3)*132 + i] = av.w;
      Bst[(k+0)*132 + i] = bv.x; Bst[(k+1)*132 + i] = bv.y;
      Bst[(k+2)*132 + i] = bv.z; Bst[(k+3)*132 + i] = bv.w;
    }
  }
  __syncthreads();
  int tx = t & 15, ty = t >> 4;
  int i0 = ty*8;
  int jA = tx*4, jB = 64 + tx*4;
  ull acc[8][4];
  #pragma unroll
  for (int ii = 0; ii < 8; ii++)
    #pragma unroll
    for (int jj = 0; jj < 4; jj++) acc[ii][jj] = 0ull;
  #pragma unroll 16
  for (int k = 0; k < 64; k++){
    const float* ar = Ast + k*132 + i0;
    float4 aA = *(const float4*)ar;
    float4 aB = *(const float4*)(ar + 4);
    ulonglong2 bA = *(const ulonglong2*)&Bst[k*132 + jA];
    ulonglong2 bB = *(const ulonglong2*)&Bst[k*132 + jB];
    float av[8] = {aA.x, aA.y, aA.z, aA.w, aB.x, aB.y, aB.z, aB.w};
    #pragma unroll
    for (int ii = 0; ii < 8; ii++){
      ull ad = dup2(av[ii]);
      acc[ii][0] = ffma2(ad, bA.x, acc[ii][0]);
      acc[ii][1] = ffma2(ad, bA.y, acc[ii][1]);
      acc[ii][2] = ffma2(ad, bB.x, acc[ii][2]);
      acc[ii][3] = ffma2(ad, bB.y, acc[ii][3]);
    }
  }
  __syncthreads();     // all warps done reading Ast/Bst
  #pragma unroll
  for (int ii = 0; ii < 8; ii++){
    float v0,v1,v2,v3,v4,v5,v6,v7;
    unpack2(acc[ii][0], v0, v1);
    unpack2(acc[ii][1], v2, v3);
    unpack2(acc[ii][2], v4, v5);
    unpack2(acc[ii][3], v6, v7);
    float* srow = sc + (i0+ii)*132;
    *(float4*)&srow[jA] = make_float4(v0,v1,v2,v3);
    *(float4*)&srow[jB] = make_float4(v4,v5,v6,v7);
  }
  __syncthreads();     // tile visible to all

  // ---- local top-20 per row ----
  int half = t >> 7;       // 0: rows bi..bi+127 (direct), 1: rows bj.. (transpose)
  int r = t & 127;
  if (half == 0 || ti != tj){
    float cv[20]; int ci[20];
    #pragma unroll
    for (int s = 0; s < 20; s++){ cv[s] = -CUDART_INF_F; ci[s] = 0x7fffffff; }
    float vmin = -CUDART_INF_F; int mi = 0x7fffffff; int mslot = 0;
    if (half == 0){
      const float* srow = sc + r*132;
      #pragma unroll 1
      for (int c4 = 0; c4 < 32; c4++){
        float4 q = *(const float4*)&srow[c4*4];
        upd20(q.x, c4*4+0, cv, ci, vmin, mi, mslot);
        upd20(q.y, c4*4+1, cv, ci, vmin, mi, mslot);
        upd20(q.z, c4*4+2, cv, ci, vmin, mi, mslot);
        upd20(q.w, c4*4+3, cv, ci, vmin, mi, mslot);
      }
    } else {
      #pragma unroll 1
      for (int c = 0; c < 128; c++)
        upd20(sc[c*132 + r], c, cv, ci, vmin, mi, mslot);
    }
    int slice   = (half == 0) ? tj : ti;
    int rowbase = (half == 0) ? bi : bj;
    int colbase = slice*128;
    int grow = b*NN + rowbase + r;
    #pragma unroll 1
    for (int s = 0; s < 20; s++){
      g_cv[(slice*KK + s)*NROWS + grow] = cv[s];
      g_ci[(slice*KK + s)*NROWS + grow] = colbase + ci[s];
    }
  }
}

// ---------------- K6: merge 8x20 candidates -> global top-20 (thread per row) ----------------
__global__ void __launch_bounds__(256) k_topk(){
  int row = blockIdx.x*256 + threadIdx.x;
  float cv[20]; int ci[20];
  #pragma unroll
  for (int s = 0; s < 20; s++){ cv[s] = -CUDART_INF_F; ci[s] = 0x7fffffff; }
  float vmin = -CUDART_INF_F; int mi = 0x7fffffff; int mslot = 0;
  #pragma unroll 4
  for (int c = 0; c < NSLICE*KK; c++){
    float v = g_cv[c*NROWS + row];
    int j  = g_ci[c*NROWS + row];
    upd20(v, j, cv, ci, vmin, mi, mslot);
  }
  float* otv = g_tv + row*KK;
  int*   oti = g_ti + row*KK;
  #pragma unroll 1
  for (int s = 0; s < 20; s++){ otv[s] = cv[s]; oti[s] = ci[s]; }
}

// ---------------- K7: GAT attention + aggregation ----------------
__global__ void __launch_bounds__(256) k_gat(const float* __restrict__ bgnn){
  __shared__ int   sidx[4][KK];
  __shared__ float stv[4][KK];
  __shared__ float sw[4][KK+1];
  int t = threadIdx.x;
  int g = t >> 6, d = t & 63;
  int row = blockIdx.x*4 + g;
  int b = row >> 10, i = row & (NN-1);
  if (d < KK){
    stv[g][d] = g_tv[row*KK + d];
    sidx[g][d] = g_ti[row*KK + d];
  }
  __syncthreads();
  if (d < 32){
    int lane = d;
    float si = g_si[row];
    float a;
    if (lane < KK){
      int j = sidx[g][lane];
      float sj = g_sj[b*NN + j];
      a = (j == i) ? -CUDART_INF_F : lrelu(si + sj);
    } else if (lane == KK){
      a = lrelu(si + g_sj[row]);
    } else a = -CUDART_INF_F;
    float m = a;
    #pragma unroll
    for (int off = 16; off > 0; off >>= 1) m = fmaxf(m, __shfl_xor_sync(0xffffffffu, m, off));
    float e = (lane <= KK) ? expf(a - m) : 0.f;
    float s = e;
    #pragma unroll
    for (int off = 16; off > 0; off >>= 1) s += __shfl_xor_sync(0xffffffffu, s, off);
    float att = e / s;
    float tvv = (lane < KK) ? stv[g][lane] : -CUDART_INF_F;
    float m2 = tvv;
    #pragma unroll
    for (int off = 16; off > 0; off >>= 1) m2 = fmaxf(m2, __shfl_xor_sync(0xffffffffu, m2, off));
    float e2 = (lane < KK) ? expf(tvv - m2) : 0.f;
    float s2 = e2;
    #pragma unroll
    for (int off = 16; off > 0; off >>= 1) s2 += __shfl_xor_sync(0xffffffffu, s2, off);
    if (lane <= KK)
      sw[g][lane] = (lane < KK) ? att * (e2 / s2) : att;
  }
  __syncthreads();
  int idx[KK];
  #pragma unroll
  for (int k = 0; k < KK; k++) idx[k] = sidx[g][k];
  const float* xb = g_xlin + (size_t)b*NN*DD;
  float acc = sw[g][KK] * g_xlin[row*DD + d];
  #pragma unroll
  for (int k = 0; k < KK; k++)
    acc = fmaf(sw[g][k], xb[(size_t)idx[k]*DD + d], acc);
  acc += bgnn[d];
  g_gnn[row*DD + d] = acc;
}

// ---------------- K8: BN1 stats ----------------
__global__ void __launch_bounds__(256) k_stats1(){
  __shared__ float ss[256], sq[256];
  int t = threadIdx.x;
  int c = t >> 6, d = t & 63;
  float s = 0.f, q = 0.f;
  int base = blockIdx.x * 256;
  for (int it = 0; it < 64; it++){
    int row = base + it*4 + c;
    float x = g_gnn[row*DD + d];
    s += x;
    q = fmaf(x, x, q);
  }
  ss[t] = s; sq[t] = q;
  __syncthreads();
  if (t < 64){
    double S = (double)ss[t] + ss[t+64] + ss[t+128] + ss[t+192];
    double Q = (double)sq[t] + sq[t+64] + sq[t+128] + sq[t+192];
    atomicAdd(&g_stats[d], S);
    atomicAdd(&g_stats[DD + d], Q);
  }
}

// ---------------- K9: BN2 stats from recomputed y ----------------
__global__ void __launch_bounds__(256) k_bn1mul(const float* __restrict__ g1,
    const float* __restrict__ be1, const float* __restrict__ net){
  __shared__ float ss[256], sq[256];
  int t = threadIdx.x;
  int c = t >> 6, d = t & 63;
  double inv = 1.0 / (double)NROWS;
  double mu = g_stats[d] * inv;
  double var = g_stats[DD + d] * inv - mu*mu;
  float scale = g1[d] * rsqrtf((float)var + BN_EPS);
  float shift = be1[d] - (float)mu * scale;
  float s = 0.f, q = 0.f;
  int base = blockIdx.x * 256;
  for (int it = 0; it < 64; it++){
    int row = base + it*4 + c;
    float x = g_gnn[row*DD + d];
    float gv = fmaxf(fmaf(x, scale, shift), 0.f);
    float y = gv * net[(row & (NN-1))*DD + d];
    s += y;
    q = fmaf(y, y, q);
  }
  ss[t] = s; sq[t] = q;
  __syncthreads();
  if (t < 64){
    double S = (double)ss[t] + ss[t+64] + ss[t+128] + ss[t+192];
    double Q = (double)sq[t] + sq[t+64] + sq[t+128] + sq[t+192];
    atomicAdd(&g_stats[2*DD + d], S);
    atomicAdd(&g_stats[3*DD + d], Q);
  }
}

// ---------------- K10: BN2 + relu + output head ----------------
__global__ void __launch_bounds__(256) k_head(const float* __restrict__ g1,
    const float* __restrict__ be1, const float* __restrict__ net,
    const float* __restrict__ g2, const float* __restrict__ be2,
    const float* __restrict__ Wo, const float* __restrict__ bo,
    float* __restrict__ dout){
  int warp = threadIdx.x >> 5;
  int lane = threadIdx.x & 31;
  int row = blockIdx.x*8 + warp;
  int n = row & (NN-1);
  double inv = 1.0 / (double)NROWS;
  float acc = 0.f;
  #pragma unroll
  for (int h = 0; h < 2; h++){
    int d = lane + h*32;
    double mu1 = g_stats[d] * inv;
    double var1 = g_stats[DD + d] * inv - mu1*mu1;
    float sc1 = g1[d] * rsqrtf((float)var1 + BN_EPS);
    float sh1 = be1[d] - (float)mu1 * sc1;
    double mu2 = g_stats[2*DD + d] * inv;
    double var2 = g_stats[3*DD + d] * inv - mu2*mu2;
    float sc2 = g2[d] * rsqrtf((float)var2 + BN_EPS);
    float sh2 = be2[d] - (float)mu2 * sc2;
    float x = g_gnn[row*DD + d];
    float gv = fmaxf(fmaf(x, sc1, sh1), 0.f);
    float y = gv * net[n*DD + d];
    float r = fmaxf(fmaf(y, sc2, sh2), 0.f);
    acc = fmaf(r, Wo[d], acc);
  }
  #pragma unroll
  for (int off = 16; off > 0; off >>= 1)
    acc += __shfl_down_sync(0xffffffffu, acc, off);
  if (lane == 0) dout[row] = acc + bo[0];
}

// ---------------- launch ----------------
extern "C" void kernel_launch(void* const* d_in, const int* in_sizes, int n_in,
                              void* d_out, int out_size) {
  const float* data   = (const float*)d_in[0];
  const float* gum    = (const float*)d_in[1];
  const float* Wc     = (const float*)d_in[2];
  const float* bc     = (const float*)d_in[3];
  const float* Wap    = (const float*)d_in[4];
  const float* bap    = (const float*)d_in[5];
  const float* Wav    = (const float*)d_in[6];
  const float* Wr     = (const float*)d_in[7];
  const float* br     = (const float*)d_in[8];
  const float* ebase  = (const float*)d_in[9];
  const float* lru    = (const float*)d_in[10];
  const float* lrv    = (const float*)d_in[11];
  const float* Wg     = (const float*)d_in[12];
  const float* ai     = (const float*)d_in[13];
  const float* aj     = (const float*)d_in[14];
  const float* aei    = (const float*)d_in[15];
  const float* aej    = (const float*)d_in[16];
  const float* bgnn   = (const float*)d_in[17];
  const float* g1     = (const float*)d_in[18];
  const float* be1    = (const float*)d_in[19];
  const float* net    = (const float*)d_in[20];
  const float* g2     = (const float*)d_in[21];
  const float* be2    = (const float*)d_in[22];
  const float* Wo     = (const float*)d_in[23];
  const float* bo     = (const float*)d_in[24];

  float* out    = (float*)d_out;              // [B,N]   32768
  float* hs_out = out + NROWS;                // [B,D]   2048
  float* ps_out = hs_out + BB*DD;             // [B,M]   128

  const int SC_SMEM = 2*64*132*4;             // 67584 B (also exactly 128x132 floats)
  cudaFuncSetAttribute(k_scores, cudaFuncAttributeMaxDynamicSharedMemorySize, SC_SMEM);

  k_cond<<<NROWS/8, 256>>>(data, Wc, bc, Wap, bap, Wav, Wg, ebase, lru, lrv);
  k_hsys<<<dim3(HCHUNK, BB), 256>>>();
  k_route<<<BB, 64>>>(Wr, br, gum, hs_out, ps_out);
  k_mixed<<<NROWS/8, 256>>>(ai, aj, aei, aej);
  k_scores<<<dim3(36, 1, BB), 256, SC_SMEM>>>();
  k_topk<<<NROWS/256, 256>>>();
  k_gat<<<NROWS/4, 256>>>(bgnn);
  k_stats1<<<128, 256>>>();
  k_bn1mul<<<128, 256>>>(g1, be1, net);
  k_head<<<NROWS/8, 256>>>(g1, be1, net, g2, be2, Wo, bo, out);
}

// round 16
// speedup vs baseline: 4.8100x; 4.8100x over previous
#include <cuda_runtime.h>
#include <math_constants.h>
#include <math.h>

#define BB 32
#define NN 1024
#define FF 10
#define DD 64
#define MM 4
#define RR 8
#define KK 20
#define NROWS (BB*NN)           // 32768
#define BN_EPS 1e-5f
#define HCHUNK 16

typedef unsigned long long ull;

// ---------------- scratch (device globals; no runtime allocation) ----------------
__device__ float g_hit[NROWS*DD];
__device__ float g_xlin[NROWS*DD];
__device__ float g_eit[NROWS];
__device__ float g_hpart[HCHUNK*BB*DD];
__device__ float g_dpart[HCHUNK*BB];
__device__ float g_pih[BB*MM];
__device__ float g_proto[MM*NN*DD];
__device__ float g_mixed[NROWS*DD];
__device__ float g_si[NROWS];
__device__ float g_sj[NROWS];
__device__ float g_scores[(size_t)BB*NN*NN];   // 128 MiB
__device__ float g_tv[NROWS*KK];
__device__ int   g_ti[NROWS*KK];
__device__ float g_gnn[NROWS*DD];
__device__ double g_stats[4*DD];

// ---------------- helpers ----------------
__device__ __forceinline__ float nanfix(float x){
  if (isnan(x)) return 0.f;
  if (isinf(x)) return x > 0.f ? 1e4f : -1e4f;
  return x;
}
__device__ __forceinline__ float lrelu(float x){ return x >= 0.f ? x : 0.2f*x; }

__device__ __forceinline__ ull ffma2(ull a, ull b, ull c){
  ull d;
  asm("fma.rn.f32x2 %0, %1, %2, %3;" : "=l"(d) : "l"(a), "l"(b), "l"(c));
  return d;
}
__device__ __forceinline__ ull dup2(float a){
  ull r;
  asm("mov.b64 %0, {%1, %1};" : "=l"(r) : "f"(a));
  return r;
}
__device__ __forceinline__ void unpack2(ull v, float& lo, float& hi){
  asm("mov.b64 {%0, %1}, %2;" : "=f"(lo), "=f"(hi) : "l"(v));
}

// ---------------- K1: cond MLP (h_it, e_it) + x_lin + proto fold + stats zero ----------------
__global__ void __launch_bounds__(256) k_cond(const float* __restrict__ data,
    const float* __restrict__ Wc, const float* __restrict__ bc,
    const float* __restrict__ Wap, const float* __restrict__ bap,
    const float* __restrict__ Wav, const float* __restrict__ Wg,
    const float* __restrict__ ebase, const float* __restrict__ lru,
    const float* __restrict__ lrv){
  __shared__ float Wap_s[DD*DD];
  __shared__ float Wc_s[FF*DD];
  __shared__ float Wg_s[FF*DD];
  __shared__ float hbuf[8][DD];
  int t = threadIdx.x;
  if (blockIdx.x == 0) g_stats[t] = 0.0;
  for (int e = t; e < DD*DD; e += 256) Wap_s[e] = Wap[e];
  for (int e = t; e < FF*DD; e += 256){ Wc_s[e] = Wc[e]; Wg_s[e] = Wg[e]; }
  int warp = t >> 5, lane = t & 31;
  int row = blockIdx.x*8 + warp;
  // folded k_proto: blocks 0..511 each handle 8 proto rows
  if (blockIdx.x < MM*NN/8){
    int rown = blockIdx.x*8 + warp;        // m*NN + n
    int m = rown >> 10, n = rown & (NN-1);
    int pd0 = lane, pd1 = lane + 32;
    float p0 = ebase[n*DD+pd0], p1 = ebase[n*DD+pd1];
    #pragma unroll
    for (int r = 0; r < RR; r++){
      float u = lru[rown*RR + r];
      p0 = fmaf(u, lrv[(m*RR+r)*DD+pd0], p0);
      p1 = fmaf(u, lrv[(m*RR+r)*DD+pd1], p1);
    }
    g_proto[rown*DD+pd0] = p0;
    g_proto[rown*DD+pd1] = p1;
  }
  __syncthreads();
  const float* dr = data + row*FF;
  float x[FF];
  #pragma unroll
  for (int f = 0; f < FF; f++) x[f] = dr[f];
  int d0 = lane, d1 = lane + 32;
  float h0 = bc[d0], h1 = bc[d1], xl0 = 0.f, xl1 = 0.f;
  #pragma unroll
  for (int f = 0; f < FF; f++){
    h0  = fmaf(x[f], Wc_s[f*DD+d0], h0);
    h1  = fmaf(x[f], Wc_s[f*DD+d1], h1);
    xl0 = fmaf(x[f], Wg_s[f*DD+d0], xl0);
    xl1 = fmaf(x[f], Wg_s[f*DD+d1], xl1);
  }
  g_hit[row*DD+d0] = h0;  g_hit[row*DD+d1] = h1;
  g_xlin[row*DD+d0] = xl0; g_xlin[row*DD+d1] = xl1;
  hbuf[warp][d0] = h0; hbuf[warp][d1] = h1;
  __syncwarp();
  float a0 = bap[d0], a1 = bap[d1];
  #pragma unroll 16
  for (int e = 0; e < DD; e++){
    float he = hbuf[warp][e];
    a0 = fmaf(he, Wap_s[e*DD+d0], a0);
    a1 = fmaf(he, Wap_s[e*DD+d1], a1);
  }
  a0 = lrelu(a0); a1 = lrelu(a1);
  float ts = a0*Wav[d0] + a1*Wav[d1];
  #pragma unroll
  for (int off = 16; off > 0; off >>= 1) ts += __shfl_xor_sync(0xffffffffu, ts, off);
  if (lane == 0) g_eit[row] = nanfix(ts);
}

// ---------------- K2: h_sys partial sums + partial denominators (no-max softmax) ----------------
__global__ void __launch_bounds__(256) k_hsys(){
  int chunk = blockIdx.x;            // 0..15 (64 rows each)
  int b = blockIdx.y;
  int t = threadIdx.x;
  int d = t & 63, r4 = t >> 6;
  __shared__ float we[64];
  __shared__ float red[256];
  int n0 = chunk*64;
  const float* e = g_eit + b*NN + n0;
  if (t < 64) we[t] = expf(e[t]);
  __syncthreads();
  const float* h = g_hit + ((size_t)b*NN + n0)*DD;
  float acc = 0.f;
  #pragma unroll 4
  for (int r = r4; r < 64; r += 4)
    acc = fmaf(we[r], h[r*DD + d], acc);
  red[t] = acc; __syncthreads();
  if (t < 64)
    g_hpart[(chunk*BB + b)*DD + d] = red[d] + red[d+64] + red[d+128] + red[d+192];
  if (t >= 64 && t < 96){
    int lane = t - 64;
    float s = we[lane] + we[lane+32];
    #pragma unroll
    for (int off = 16; off > 0; off >>= 1) s += __shfl_xor_sync(0xffffffffu, s, off);
    if (lane == 0) g_dpart[chunk*BB + b] = s;
  }
}

// ---------------- K3: finalize h_sys + gumbel top-2 routing ----------------
__global__ void __launch_bounds__(64) k_route(const float* __restrict__ Wr,
    const float* __restrict__ br, const float* __restrict__ gum,
    float* __restrict__ hs_out, float* __restrict__ ps_out){
  int b = blockIdx.x, t = threadIdx.x;
  __shared__ float shs[DD];
  __shared__ float slog[MM];
  float s = 0.f;
  #pragma unroll
  for (int c = 0; c < HCHUNK; c++) s += g_hpart[(c*BB + b)*DD + t];
  float den = 0.f;
  #pragma unroll
  for (int c = 0; c < HCHUNK; c++) den += g_dpart[c*BB + b];
  float hs = s / den;
  shs[t] = hs;
  hs_out[b*DD + t] = hs;
  __syncthreads();
  if (t < MM){
    float lg = br[t] + gum[b*MM + t];
    #pragma unroll 8
    for (int dd2 = 0; dd2 < DD; dd2++) lg = fmaf(shs[dd2], Wr[dd2*MM + t], lg);
    slog[t] = lg;
  }
  __syncthreads();
  if (t == 0){
    float mm = slog[0];
    #pragma unroll
    for (int i = 1; i < MM; i++) mm = fmaxf(mm, slog[i]);
    float p[MM]; float sp = 0.f;
    #pragma unroll
    for (int i = 0; i < MM; i++){ p[i] = expf(slog[i] - mm); sp += p[i]; }
    #pragma unroll
    for (int i = 0; i < MM; i++){ p[i] /= sp; ps_out[b*MM + i] = p[i]; }
    int i1 = 0;
    #pragma unroll
    for (int i = 1; i < MM; i++) if (p[i] > p[i1]) i1 = i;
    int i2 = -1;
    #pragma unroll
    for (int i = 0; i < MM; i++){
      if (i == i1) continue;
      if (i2 < 0 || p[i] > p[i2]) i2 = i;
    }
    float nrm = fmaxf(p[i1] + p[i2], 1e-12f);
    #pragma unroll
    for (int i = 0; i < MM; i++) g_pih[b*MM + i] = 0.f;
    g_pih[b*MM + i1] = p[i1] / nrm;
    g_pih[b*MM + i2] = p[i2] / nrm;
  }
}

// ---------------- K4: mixed = pi @ proto, + s_i / s_j ----------------
__global__ void __launch_bounds__(256) k_mixed(const float* __restrict__ ai,
    const float* __restrict__ aj, const float* __restrict__ aei,
    const float* __restrict__ aej){
  int t = threadIdx.x, warp = t >> 5, lane = t & 31;
  int row = blockIdx.x*8 + warp;
  int b = row >> 10, n = row & (NN-1);
  int d0 = lane, d1 = lane + 32;
  float pi0 = g_pih[b*MM+0], pi1 = g_pih[b*MM+1];
  float pi2 = g_pih[b*MM+2], pi3 = g_pih[b*MM+3];
  float mx0, mx1;
  {
    const float* p0 = g_proto + (0*NN+n)*DD;
    const float* p1 = g_proto + (1*NN+n)*DD;
    const float* p2 = g_proto + (2*NN+n)*DD;
    const float* p3 = g_proto + (3*NN+n)*DD;
    mx0 = pi0*p0[d0] + pi1*p1[d0] + pi2*p2[d0] + pi3*p3[d0];
    mx1 = pi0*p0[d1] + pi1*p1[d1] + pi2*p2[d1] + pi3*p3[d1];
  }
  mx0 = nanfix(mx0); mx1 = nanfix(mx1);
  g_mixed[row*DD+d0] = mx0;
  g_mixed[row*DD+d1] = mx1;
  float xl0 = g_xlin[row*DD+d0], xl1 = g_xlin[row*DD+d1];
  float r1 = xl0*ai[d0] + mx0*aei[d0] + xl1*ai[d1] + mx1*aei[d1];
  float r2 = xl0*aj[d0] + mx0*aej[d0] + xl1*aj[d1] + mx1*aej[d1];
  #pragma unroll
  for (int off = 16; off > 0; off >>= 1){
    r1 += __shfl_xor_sync(0xffffffffu, r1, off);
    r2 += __shfl_xor_sync(0xffffffffu, r2, off);
  }
  if (lane == 0){ g_si[row] = r1; g_sj[row] = r2; }
}

// ---------------- K5: scores = mixed @ mixed^T, symmetric, f32x2, 128x128 tiles ----------------
// j-microtile split into two 4-wide halves (tx*4 and 64+tx*4): 16B lane stride in
// smem B loads -> conflict-free LDS.128. Same FFMA2 count, same k-order => bit-identical C.
__global__ void __launch_bounds__(256, 2) k_scores(){
  extern __shared__ float smem[];
  float* Ast = smem;               // [64][132]
  float* Bst = smem + 64*132;      // [64][132]
  int b = blockIdx.z;
  int p = blockIdx.x, ti = 0;
  while (p >= 8 - ti){ p -= 8 - ti; ti++; }
  int tj = ti + p;
  int bi = ti*128, bj = tj*128;
  int t = threadIdx.x;
  const float* A  = g_mixed + ((size_t)b*NN + bi)*DD;
  const float* Bm = g_mixed + ((size_t)b*NN + bj)*DD;
  {
    int i = t >> 1, kh = (t & 1) * 32;
    const float4* a4 = (const float4*)(A  + i*DD + kh);
    const float4* b4 = (const float4*)(Bm + i*DD + kh);
    #pragma unroll
    for (int q = 0; q < 8; q++){
      float4 av = a4[q], bv = b4[q];
      int k = kh + q*4;
      Ast[(k+0)*132 + i] = av.x; Ast[(k+1)*132 + i] = av.y;
      Ast[(k+2)*132 + i] = av.z; Ast[(k+3)*132 + i] = av.w;
      Bst[(k+0)*132 + i] = bv.x; Bst[(k+1)*132 + i] = bv.y;
      Bst[(k+2)*132 + i] = bv.z; Bst[(k+3)*132 + i] = bv.w;
    }
  }
  __syncthreads();
  int tx = t & 15, ty = t >> 4;
  int i0 = ty*8;
  int jA = tx*4, jB = 64 + tx*4;
  ull acc[8][4];
  #pragma unroll
  for (int ii = 0; ii < 8; ii++)
    #pragma unroll
    for (int jj = 0; jj < 4; jj++) acc[ii][jj] = 0ull;
  #pragma unroll 16
  for (int k = 0; k < 64; k++){
    const float* ar = Ast + k*132 + i0;
    float4 aA = *(const float4*)ar;
    float4 aB = *(const float4*)(ar + 4);
    ulonglong2 bA = *(const ulonglong2*)&Bst[k*132 + jA];   // conflict-free
    ulonglong2 bB = *(const ulonglong2*)&Bst[k*132 + jB];   // conflict-free
    float av[8] = {aA.x, aA.y, aA.z, aA.w, aB.x, aB.y, aB.z, aB.w};
    #pragma unroll
    for (int ii = 0; ii < 8; ii++){
      ull ad = dup2(av[ii]);
      acc[ii][0] = ffma2(ad, bA.x, acc[ii][0]);
      acc[ii][1] = ffma2(ad, bA.y, acc[ii][1]);
      acc[ii][2] = ffma2(ad, bB.x, acc[ii][2]);
      acc[ii][3] = ffma2(ad, bB.y, acc[ii][3]);
    }
  }
  size_t baseA = ((size_t)b*NN + bi + i0)*NN + bj;
  #pragma unroll
  for (int ii = 0; ii < 8; ii++){
    float v0,v1,v2,v3,v4,v5,v6,v7;
    unpack2(acc[ii][0], v0, v1);
    unpack2(acc[ii][1], v2, v3);
    unpack2(acc[ii][2], v4, v5);
    unpack2(acc[ii][3], v6, v7);
    float* C = g_scores + baseA + (size_t)ii*NN;
    *(float4*)&C[jA] = make_float4(v0,v1,v2,v3);
    *(float4*)&C[jB] = make_float4(v4,v5,v6,v7);
  }
  if (ti != tj){
    float v[8][8];
    #pragma unroll
    for (int ii = 0; ii < 8; ii++)
      #pragma unroll
      for (int jp = 0; jp < 4; jp++)
        unpack2(acc[ii][jp], v[ii][2*jp], v[ii][2*jp+1]);
    #pragma unroll
    for (int jj = 0; jj < 8; jj++){
      int col = (jj < 4) ? (jA + jj) : (jB + jj - 4);
      float* C2 = g_scores + ((size_t)b*NN + bj + col)*NN + bi + i0;
      *(float4*)&C2[0] = make_float4(v[0][jj], v[1][jj], v[2][jj], v[3][jj]);
      *(float4*)&C2[4] = make_float4(v[4][jj], v[5][jj], v[6][jj], v[7][jj]);
    }
  }
}

// ---------------- K6: top-20 per row (warp per row, vectorized loads) ----------------
// slot s (0..31) of a lane maps to global j = (s>>2)*128 + lane*4 + (s&3);
// ascending s == ascending j per lane, so tie-breaks match lax.top_k.
// All top-k state is statically-indexed registers (sorted top-3 cache + bitmask);
// dynamic-indexed candidate arrays spill to local memory (R15 lesson).
__global__ void __launch_bounds__(256) k_topk(){
  int warp = threadIdx.x >> 5, lane = threadIdx.x & 31;
  int row = blockIdx.x*8 + warp;
  const float4* srow = (const float4*)(g_scores + (size_t)row*NN);
  float v[32];
  #pragma unroll
  for (int c = 0; c < 8; c++){
    float4 q = srow[c*32 + lane];
    v[c*4+0] = q.x; v[c*4+1] = q.y; v[c*4+2] = q.z; v[c*4+3] = q.w;
  }
  float c0v = -CUDART_INF_F, c1v = -CUDART_INF_F, c2v = -CUDART_INF_F;
  int c0s = 0, c1s = 0, c2s = 0;
  #pragma unroll
  for (int s = 0; s < 32; s++){
    float x = v[s];
    if (x > c2v){
      if (x > c1v){
        c2v = c1v; c2s = c1s;
        if (x > c0v){ c1v = c0v; c1s = c0s; c0v = x; c0s = s; }
        else        { c1v = x; c1s = s; }
      } else { c2v = x; c2s = s; }
    }
  }
  unsigned used = 0u;
  int p = 0;
  int cs = c0s;
  float candv = c0v;
  int candg = ((c0s >> 2) << 7) + (lane << 2) + (c0s & 3);
  float* otv = g_tv + row*KK;
  int*   oti = g_ti + row*KK;
  for (int k = 0; k < KK; k++){
    float bv = candv; int bg = candg;
    #pragma unroll
    for (int off = 16; off > 0; off >>= 1){
      float ov = __shfl_xor_sync(0xffffffffu, bv, off);
      int   og = __shfl_xor_sync(0xffffffffu, bg, off);
      if (ov > bv || (ov == bv && og < bg)){ bv = ov; bg = og; }
    }
    if (lane == 0){ otv[k] = bv; oti[k] = bg; }
    if (bg == candg){
      used |= 1u << cs;
      p++;
      if (p == 1){ cs = c1s; candv = c1v; candg = ((c1s>>2)<<7) + (lane<<2) + (c1s&3); }
      else if (p == 2){ cs = c2s; candv = c2v; candg = ((c2s>>2)<<7) + (lane<<2) + (c2s&3); }
      else {
        candv = -CUDART_INF_F; cs = -1;
        #pragma unroll
        for (int s = 0; s < 32; s++){
          if (!((used >> s) & 1u)){
            float x = v[s];
            if (x > candv){ candv = x; cs = s; }
          }
        }
        candg = (cs >= 0) ? (((cs>>2)<<7) + (lane<<2) + (cs&3)) : ((1<<20) + lane);
      }
    }
  }
}

// ---------------- K7: GAT attention + aggregation ----------------
__global__ void __launch_bounds__(256) k_gat(const float* __restrict__ bgnn){
  __shared__ int   sidx[4][KK];
  __shared__ float stv[4][KK];
  __shared__ float sw[4][KK+1];
  int t = threadIdx.x;
  int g = t >> 6, d = t & 63;
  int row = blockIdx.x*4 + g;
  int b = row >> 10, i = row & (NN-1);
  if (d < KK){
    stv[g][d] = g_tv[row*KK + d];
    sidx[g][d] = g_ti[row*KK + d];
  }
  __syncthreads();
  if (d < 32){
    int lane = d;
    float si = g_si[row];
    float a;
    if (lane < KK){
      int j = sidx[g][lane];
      float sj = g_sj[b*NN + j];
      a = (j == i) ? -CUDART_INF_F : lrelu(si + sj);
    } else if (lane == KK){
      a = lrelu(si + g_sj[row]);
    } else a = -CUDART_INF_F;
    float m = a;
    #pragma unroll
    for (int off = 16; off > 0; off >>= 1) m = fmaxf(m, __shfl_xor_sync(0xffffffffu, m, off));
    float e = (lane <= KK) ? expf(a - m) : 0.f;
    float s = e;
    #pragma unroll
    for (int off = 16; off > 0; off >>= 1) s += __shfl_xor_sync(0xffffffffu, s, off);
    float att = e / s;
    float tvv = (lane < KK) ? stv[g][lane] : -CUDART_INF_F;
    float m2 = tvv;
    #pragma unroll
    for (int off = 16; off > 0; off >>= 1) m2 = fmaxf(m2, __shfl_xor_sync(0xffffffffu, m2, off));
    float e2 = (lane < KK) ? expf(tvv - m2) : 0.f;
    float s2 = e2;
    #pragma unroll
    for (int off = 16; off > 0; off >>= 1) s2 += __shfl_xor_sync(0xffffffffu, s2, off);
    if (lane <= KK)
      sw[g][lane] = (lane < KK) ? att * (e2 / s2) : att;
  }
  __syncthreads();
  // prefetch indices to registers, fully unroll gather -> high MLP
  int idx[KK];
  #pragma unroll
  for (int k = 0; k < KK; k++) idx[k] = sidx[g][k];
  const float* xb = g_xlin + (size_t)b*NN*DD;
  float acc = sw[g][KK] * g_xlin[row*DD + d];
  #pragma unroll
  for (int k = 0; k < KK; k++)
    acc = fmaf(sw[g][k], xb[(size_t)idx[k]*DD + d], acc);
  acc += bgnn[d];
  g_gnn[row*DD + d] = acc;
}

// ---------------- K8: BN1 stats ----------------
__global__ void __launch_bounds__(256) k_stats1(){
  __shared__ float ss[256], sq[256];
  int t = threadIdx.x;
  int c = t >> 6, d = t & 63;
  float s = 0.f, q = 0.f;
  int base = blockIdx.x * 256;
  for (int it = 0; it < 64; it++){
    int row = base + it*4 + c;
    float x = g_gnn[row*DD + d];
    s += x;
    q = fmaf(x, x, q);
  }
  ss[t] = s; sq[t] = q;
  __syncthreads();
  if (t < 64){
    double S = (double)ss[t] + ss[t+64] + ss[t+128] + ss[t+192];
    double Q = (double)sq[t] + sq[t+64] + sq[t+128] + sq[t+192];
    atomicAdd(&g_stats[d], S);
    atomicAdd(&g_stats[DD + d], Q);
  }
}

// ---------------- K9: BN2 stats from recomputed y ----------------
__global__ void __launch_bounds__(256) k_bn1mul(const float* __restrict__ g1,
    const float* __restrict__ be1, const float* __restrict__ net){
  __shared__ float ss[256], sq[256];
  int t = threadIdx.x;
  int c = t >> 6, d = t & 63;
  double inv = 1.0 / (double)NROWS;
  double mu = g_stats[d] * inv;
  double var = g_stats[DD + d] * inv - mu*mu;
  float scale = g1[d] * rsqrtf((float)var + BN_EPS);
  float shift = be1[d] - (float)mu * scale;
  float s = 0.f, q = 0.f;
  int base = blockIdx.x * 256;
  for (int it = 0; it < 64; it++){
    int row = base + it*4 + c;
    float x = g_gnn[row*DD + d];
    float gv = fmaxf(fmaf(x, scale, shift), 0.f);
    float y = gv * net[(row & (NN-1))*DD + d];
    s += y;
    q = fmaf(y, y, q);
  }
  ss[t] = s; sq[t] = q;
  __syncthreads();
  if (t < 64){
    double S = (double)ss[t] + ss[t+64] + ss[t+128] + ss[t+192];
    double Q = (double)sq[t] + sq[t+64] + sq[t+128] + sq[t+192];
    atomicAdd(&g_stats[2*DD + d], S);
    atomicAdd(&g_stats[3*DD + d], Q);
  }
}

// ---------------- K10: BN2 + relu + output head ----------------
__global__ void __launch_bounds__(256) k_head(const float* __restrict__ g1,
    const float* __restrict__ be1, const float* __restrict__ net,
    const float* __restrict__ g2, const float* __restrict__ be2,
    const float* __restrict__ Wo, const float* __restrict__ bo,
    float* __restrict__ dout){
  int warp = threadIdx.x >> 5;
  int lane = threadIdx.x & 31;
  int row = blockIdx.x*8 + warp;
  int n = row & (NN-1);
  double inv = 1.0 / (double)NROWS;
  float acc = 0.f;
  #pragma unroll
  for (int h = 0; h < 2; h++){
    int d = lane + h*32;
    double mu1 = g_stats[d] * inv;
    double var1 = g_stats[DD + d] * inv - mu1*mu1;
    float sc1 = g1[d] * rsqrtf((float)var1 + BN_EPS);
    float sh1 = be1[d] - (float)mu1 * sc1;
    double mu2 = g_stats[2*DD + d] * inv;
    double var2 = g_stats[3*DD + d] * inv - mu2*mu2;
    float sc2 = g2[d] * rsqrtf((float)var2 + BN_EPS);
    float sh2 = be2[d] - (float)mu2 * sc2;
    float x = g_gnn[row*DD + d];
    float gv = fmaxf(fmaf(x, sc1, sh1), 0.f);
    float y = gv * net[n*DD + d];
    float r = fmaxf(fmaf(y, sc2, sh2), 0.f);
    acc = fmaf(r, Wo[d], acc);
  }
  #pragma unroll
  for (int off = 16; off > 0; off >>= 1)
    acc += __shfl_down_sync(0xffffffffu, acc, off);
  if (lane == 0) dout[row] = acc + bo[0];
}

// ---------------- launch ----------------
extern "C" void kernel_launch(void* const* d_in, const int* in_sizes, int n_in,
                              void* d_out, int out_size) {
  const float* data   = (const float*)d_in[0];
  const float* gum    = (const float*)d_in[1];
  const float* Wc     = (const float*)d_in[2];
  const float* bc     = (const float*)d_in[3];
  const float* Wap    = (const float*)d_in[4];
  const float* bap    = (const float*)d_in[5];
  const float* Wav    = (const float*)d_in[6];
  const float* Wr     = (const float*)d_in[7];
  const float* br     = (const float*)d_in[8];
  const float* ebase  = (const float*)d_in[9];
  const float* lru    = (const float*)d_in[10];
  const float* lrv    = (const float*)d_in[11];
  const float* Wg     = (const float*)d_in[12];
  const float* ai     = (const float*)d_in[13];
  const float* aj     = (const float*)d_in[14];
  const float* aei    = (const float*)d_in[15];
  const float* aej    = (const float*)d_in[16];
  const float* bgnn   = (const float*)d_in[17];
  const float* g1     = (const float*)d_in[18];
  const float* be1    = (const float*)d_in[19];
  const float* net    = (const float*)d_in[20];
  const float* g2     = (const float*)d_in[21];
  const float* be2    = (const float*)d_in[22];
  const float* Wo     = (const float*)d_in[23];
  const float* bo     = (const float*)d_in[24];

  float* out    = (float*)d_out;              // [B,N]   32768
  float* hs_out = out + NROWS;                // [B,D]   2048
  float* ps_out = hs_out + BB*DD;             // [B,M]   128

  const int SC_SMEM = 2*64*132*4;             // 67584 B
  cudaFuncSetAttribute(k_scores, cudaFuncAttributeMaxDynamicSharedMemorySize, SC_SMEM);

  k_cond<<<NROWS/8, 256>>>(data, Wc, bc, Wap, bap, Wav, Wg, ebase, lru, lrv);
  k_hsys<<<dim3(HCHUNK, BB), 256>>>();
  k_route<<<BB, 64>>>(Wr, br, gum, hs_out, ps_out);
  k_mixed<<<NROWS/8, 256>>>(ai, aj, aei, aej);
  k_scores<<<dim3(36, 1, BB), 256, SC_SMEM>>>();
  k_topk<<<NROWS/8, 256>>>();
  k_gat<<<NROWS/4, 256>>>(bgnn);
  k_stats1<<<128, 256>>>();
  k_bn1mul<<<128, 256>>>(g1, be1, net);
  k_head<<<NROWS/8, 256>>>(g1, be1, net, g2, be2, Wo, bo, out);
}

// round 17
// speedup vs baseline: 4.8131x; 1.0007x over previous
#include <cuda_runtime.h>
#include <math_constants.h>
#include <math.h>

#define BB 32
#define NN 1024
#define FF 10
#define DD 64
#define MM 4
#define RR 8
#define KK 20
#define NROWS (BB*NN)           // 32768
#define BN_EPS 1e-5f
#define HCHUNK 16

typedef unsigned long long ull;

// ---------------- scratch (device globals; no runtime allocation) ----------------
__device__ float g_hit[NROWS*DD];
__device__ float g_xlin[NROWS*DD];
__device__ float g_eit[NROWS];
__device__ float g_hpart[HCHUNK*BB*DD];
__device__ float g_dpart[HCHUNK*BB];
__device__ int   g_cnt[BB];
__device__ float g_pih[BB*MM];
__device__ float g_proto[MM*NN*DD];
__device__ float g_mixed[NROWS*DD];
__device__ float g_si[NROWS];
__device__ float g_sj[NROWS];
__device__ float g_scores[(size_t)BB*NN*NN];   // 128 MiB
__device__ float g_tv[NROWS*KK];
__device__ int   g_ti[NROWS*KK];
__device__ float g_gnn[NROWS*DD];
__device__ double g_stats[4*DD];

// ---------------- helpers ----------------
__device__ __forceinline__ float nanfix(float x){
  if (isnan(x)) return 0.f;
  if (isinf(x)) return x > 0.f ? 1e4f : -1e4f;
  return x;
}
__device__ __forceinline__ float lrelu(float x){ return x >= 0.f ? x : 0.2f*x; }

__device__ __forceinline__ ull ffma2(ull a, ull b, ull c){
  ull d;
  asm("fma.rn.f32x2 %0, %1, %2, %3;" : "=l"(d) : "l"(a), "l"(b), "l"(c));
  return d;
}
__device__ __forceinline__ ull dup2(float a){
  ull r;
  asm("mov.b64 %0, {%1, %1};" : "=l"(r) : "f"(a));
  return r;
}
__device__ __forceinline__ void unpack2(ull v, float& lo, float& hi){
  asm("mov.b64 {%0, %1}, %2;" : "=f"(lo), "=f"(hi) : "l"(v));
}

// ---------------- K1: cond MLP (h_it, e_it) + x_lin + proto fold + zeroing ----------------
__global__ void __launch_bounds__(256) k_cond(const float* __restrict__ data,
    const float* __restrict__ Wc, const float* __restrict__ bc,
    const float* __restrict__ Wap, const float* __restrict__ bap,
    const float* __restrict__ Wav, const float* __restrict__ Wg,
    const float* __restrict__ ebase, const float* __restrict__ lru,
    const float* __restrict__ lrv){
  __shared__ float Wap_s[DD*DD];
  __shared__ float Wc_s[FF*DD];
  __shared__ float Wg_s[FF*DD];
  __shared__ float hbuf[8][DD];
  int t = threadIdx.x;
  if (blockIdx.x == 0){
    g_stats[t] = 0.0;
    if (t < BB) g_cnt[t] = 0;
  }
  for (int e = t; e < DD*DD; e += 256) Wap_s[e] = Wap[e];
  for (int e = t; e < FF*DD; e += 256){ Wc_s[e] = Wc[e]; Wg_s[e] = Wg[e]; }
  int warp = t >> 5, lane = t & 31;
  int row = blockIdx.x*8 + warp;
  // folded k_proto: blocks 0..511 each handle 8 proto rows
  if (blockIdx.x < MM*NN/8){
    int rown = blockIdx.x*8 + warp;        // m*NN + n
    int m = rown >> 10, n = rown & (NN-1);
    int pd0 = lane, pd1 = lane + 32;
    float p0 = ebase[n*DD+pd0], p1 = ebase[n*DD+pd1];
    #pragma unroll
    for (int r = 0; r < RR; r++){
      float u = lru[rown*RR + r];
      p0 = fmaf(u, lrv[(m*RR+r)*DD+pd0], p0);
      p1 = fmaf(u, lrv[(m*RR+r)*DD+pd1], p1);
    }
    g_proto[rown*DD+pd0] = p0;
    g_proto[rown*DD+pd1] = p1;
  }
  __syncthreads();
  const float* dr = data + row*FF;
  float x[FF];
  #pragma unroll
  for (int f = 0; f < FF; f++) x[f] = dr[f];
  int d0 = lane, d1 = lane + 32;
  float h0 = bc[d0], h1 = bc[d1], xl0 = 0.f, xl1 = 0.f;
  #pragma unroll
  for (int f = 0; f < FF; f++){
    h0  = fmaf(x[f], Wc_s[f*DD+d0], h0);
    h1  = fmaf(x[f], Wc_s[f*DD+d1], h1);
    xl0 = fmaf(x[f], Wg_s[f*DD+d0], xl0);
    xl1 = fmaf(x[f], Wg_s[f*DD+d1], xl1);
  }
  g_hit[row*DD+d0] = h0;  g_hit[row*DD+d1] = h1;
  g_xlin[row*DD+d0] = xl0; g_xlin[row*DD+d1] = xl1;
  hbuf[warp][d0] = h0; hbuf[warp][d1] = h1;
  __syncwarp();
  float a0 = bap[d0], a1 = bap[d1];
  #pragma unroll 16
  for (int e = 0; e < DD; e++){
    float he = hbuf[warp][e];
    a0 = fmaf(he, Wap_s[e*DD+d0], a0);
    a1 = fmaf(he, Wap_s[e*DD+d1], a1);
  }
  a0 = lrelu(a0); a1 = lrelu(a1);
  float ts = a0*Wav[d0] + a1*Wav[d1];
  #pragma unroll
  for (int off = 16; off > 0; off >>= 1) ts += __shfl_xor_sync(0xffffffffu, ts, off);
  if (lane == 0) g_eit[row] = nanfix(ts);
}

// ---------------- K2: h_sys partials + last-block finalize (route folded in) ----------------
// e_it is bounded (|e|<~1) by construction, so exp needs no max subtraction.
// Last block per batch (atomic ticket) reduces the 16 chunk partials in fixed
// order and runs the routing math -> bit-identical to the separate k_route.
__global__ void __launch_bounds__(256) k_hsys(const float* __restrict__ Wr,
    const float* __restrict__ br, const float* __restrict__ gum,
    float* __restrict__ hs_out, float* __restrict__ ps_out){
  int chunk = blockIdx.x;            // 0..15 (64 rows each)
  int b = blockIdx.y;
  int t = threadIdx.x;
  int d = t & 63, r4 = t >> 6;
  __shared__ float we[64];
  __shared__ float red[256];
  __shared__ int s_ticket;
  int n0 = chunk*64;
  const float* e = g_eit + b*NN + n0;
  if (t < 64) we[t] = expf(e[t]);
  __syncthreads();
  const float* h = g_hit + ((size_t)b*NN + n0)*DD;
  float acc = 0.f;
  #pragma unroll 4
  for (int r = r4; r < 64; r += 4)
    acc = fmaf(we[r], h[r*DD + d], acc);
  red[t] = acc; __syncthreads();
  if (t < 64)
    g_hpart[(chunk*BB + b)*DD + d] = red[d] + red[d+64] + red[d+128] + red[d+192];
  if (t >= 64 && t < 96){
    int lane = t - 64;
    float s = we[lane] + we[lane+32];
    #pragma unroll
    for (int off = 16; off > 0; off >>= 1) s += __shfl_xor_sync(0xffffffffu, s, off);
    if (lane == 0) g_dpart[chunk*BB + b] = s;
  }
  // publish partials, take a ticket; last block finalizes this batch
  __threadfence();
  __syncthreads();
  if (t == 0) s_ticket = atomicAdd(&g_cnt[b], 1);
  __syncthreads();
  if (s_ticket != HCHUNK-1) return;
  __threadfence();   // acquire: other blocks' fenced partials now visible
  __shared__ float shs[DD];
  __shared__ float slog[MM];
  if (t < 64){
    float s = 0.f;
    #pragma unroll
    for (int c = 0; c < HCHUNK; c++) s += g_hpart[(c*BB + b)*DD + t];
    float den = 0.f;
    #pragma unroll
    for (int c = 0; c < HCHUNK; c++) den += g_dpart[c*BB + b];
    float hs = s / den;
    shs[t] = hs;
    hs_out[b*DD + t] = hs;
  }
  __syncthreads();
  if (t < MM){
    float lg = br[t] + gum[b*MM + t];   // TAU = 1
    #pragma unroll 8
    for (int dd2 = 0; dd2 < DD; dd2++) lg = fmaf(shs[dd2], Wr[dd2*MM + t], lg);
    slog[t] = lg;
  }
  __syncthreads();
  if (t == 0){
    float mm = slog[0];
    #pragma unroll
    for (int i = 1; i < MM; i++) mm = fmaxf(mm, slog[i]);
    float p[MM]; float sp = 0.f;
    #pragma unroll
    for (int i = 0; i < MM; i++){ p[i] = expf(slog[i] - mm); sp += p[i]; }
    #pragma unroll
    for (int i = 0; i < MM; i++){ p[i] /= sp; ps_out[b*MM + i] = p[i]; }
    int i1 = 0;
    #pragma unroll
    for (int i = 1; i < MM; i++) if (p[i] > p[i1]) i1 = i;
    int i2 = -1;
    #pragma unroll
    for (int i = 0; i < MM; i++){
      if (i == i1) continue;
      if (i2 < 0 || p[i] > p[i2]) i2 = i;
    }
    float nrm = fmaxf(p[i1] + p[i2], 1e-12f);
    #pragma unroll
    for (int i = 0; i < MM; i++) g_pih[b*MM + i] = 0.f;
    g_pih[b*MM + i1] = p[i1] / nrm;
    g_pih[b*MM + i2] = p[i2] / nrm;
  }
}

// ---------------- K3: mixed = pi @ proto, + s_i / s_j ----------------
__global__ void __launch_bounds__(256) k_mixed(const float* __restrict__ ai,
    const float* __restrict__ aj, const float* __restrict__ aei,
    const float* __restrict__ aej){
  int t = threadIdx.x, warp = t >> 5, lane = t & 31;
  int row = blockIdx.x*8 + warp;
  int b = row >> 10, n = row & (NN-1);
  int d0 = lane, d1 = lane + 32;
  float pi0 = g_pih[b*MM+0], pi1 = g_pih[b*MM+1];
  float pi2 = g_pih[b*MM+2], pi3 = g_pih[b*MM+3];
  float mx0, mx1;
  {
    const float* p0 = g_proto + (0*NN+n)*DD;
    const float* p1 = g_proto + (1*NN+n)*DD;
    const float* p2 = g_proto + (2*NN+n)*DD;
    const float* p3 = g_proto + (3*NN+n)*DD;
    mx0 = pi0*p0[d0] + pi1*p1[d0] + pi2*p2[d0] + pi3*p3[d0];
    mx1 = pi0*p0[d1] + pi1*p1[d1] + pi2*p2[d1] + pi3*p3[d1];
  }
  mx0 = nanfix(mx0); mx1 = nanfix(mx1);
  g_mixed[row*DD+d0] = mx0;
  g_mixed[row*DD+d1] = mx1;
  float xl0 = g_xlin[row*DD+d0], xl1 = g_xlin[row*DD+d1];
  float r1 = xl0*ai[d0] + mx0*aei[d0] + xl1*ai[d1] + mx1*aei[d1];
  float r2 = xl0*aj[d0] + mx0*aej[d0] + xl1*aj[d1] + mx1*aej[d1];
  #pragma unroll
  for (int off = 16; off > 0; off >>= 1){
    r1 += __shfl_xor_sync(0xffffffffu, r1, off);
    r2 += __shfl_xor_sync(0xffffffffu, r2, off);
  }
  if (lane == 0){ g_si[row] = r1; g_sj[row] = r2; }
}

// ---------------- K4: scores = mixed @ mixed^T, symmetric, f32x2, 128x128 tiles ----------------
__global__ void __launch_bounds__(256, 2) k_scores(){
  extern __shared__ float smem[];
  float* Ast = smem;               // [64][132]
  float* Bst = smem + 64*132;      // [64][132]
  int b = blockIdx.z;
  int p = blockIdx.x, ti = 0;
  while (p >= 8 - ti){ p -= 8 - ti; ti++; }
  int tj = ti + p;
  int bi = ti*128, bj = tj*128;
  int t = threadIdx.x;
  const float* A  = g_mixed + ((size_t)b*NN + bi)*DD;
  const float* Bm = g_mixed + ((size_t)b*NN + bj)*DD;
  {
    int i = t >> 1, kh = (t & 1) * 32;
    const float4* a4 = (const float4*)(A  + i*DD + kh);
    const float4* b4 = (const float4*)(Bm + i*DD + kh);
    #pragma unroll
    for (int q = 0; q < 8; q++){
      float4 av = a4[q], bv = b4[q];
      int k = kh + q*4;
      Ast[(k+0)*132 + i] = av.x; Ast[(k+1)*132 + i] = av.y;
      Ast[(k+2)*132 + i] = av.z; Ast[(k+3)*132 + i] = av.w;
      Bst[(k+0)*132 + i] = bv.x; Bst[(k+1)*132 + i] = bv.y;
      Bst[(k+2)*132 + i] = bv.z; Bst[(k+3)*132 + i] = bv.w;
    }
  }
  __syncthreads();
  int tx = t & 15, ty = t >> 4;
  int i0 = ty*8;
  int jA = tx*4, jB = 64 + tx*4;
  ull acc[8][4];
  #pragma unroll
  for (int ii = 0; ii < 8; ii++)
    #pragma unroll
    for (int jj = 0; jj < 4; jj++) acc[ii][jj] = 0ull;
  #pragma unroll 16
  for (int k = 0; k < 64; k++){
    const float* ar = Ast + k*132 + i0;
    float4 aA = *(const float4*)ar;
    float4 aB = *(const float4*)(ar + 4);
    ulonglong2 bA = *(const ulonglong2*)&Bst[k*132 + jA];   // conflict-free
    ulonglong2 bB = *(const ulonglong2*)&Bst[k*132 + jB];   // conflict-free
    float av[8] = {aA.x, aA.y, aA.z, aA.w, aB.x, aB.y, aB.z, aB.w};
    #pragma unroll
    for (int ii = 0; ii < 8; ii++){
      ull ad = dup2(av[ii]);
      acc[ii][0] = ffma2(ad, bA.x, acc[ii][0]);
      acc[ii][1] = ffma2(ad, bA.y, acc[ii][1]);
      acc[ii][2] = ffma2(ad, bB.x, acc[ii][2]);
      acc[ii][3] = ffma2(ad, bB.y, acc[ii][3]);
    }
  }
  size_t baseA = ((size_t)b*NN + bi + i0)*NN + bj;
  #pragma unroll
  for (int ii = 0; ii < 8; ii++){
    float v0,v1,v2,v3,v4,v5,v6,v7;
    unpack2(acc[ii][0], v0, v1);
    unpack2(acc[ii][1], v2, v3);
    unpack2(acc[ii][2], v4, v5);
    unpack2(acc[ii][3], v6, v7);
    float* C = g_scores + baseA + (size_t)ii*NN;
    *(float4*)&C[jA] = make_float4(v0,v1,v2,v3);
    *(float4*)&C[jB] = make_float4(v4,v5,v6,v7);
  }
  if (ti != tj){
    float v[8][8];
    #pragma unroll
    for (int ii = 0; ii < 8; ii++)
      #pragma unroll
      for (int jp = 0; jp < 4; jp++)
        unpack2(acc[ii][jp], v[ii][2*jp], v[ii][2*jp+1]);
    #pragma unroll
    for (int jj = 0; jj < 8; jj++){
      int col = (jj < 4) ? (jA + jj) : (jB + jj - 4);
      float* C2 = g_scores + ((size_t)b*NN + bj + col)*NN + bi + i0;
      *(float4*)&C2[0] = make_float4(v[0][jj], v[1][jj], v[2][jj], v[3][jj]);
      *(float4*)&C2[4] = make_float4(v[4][jj], v[5][jj], v[6][jj], v[7][jj]);
    }
  }
}

// ---------------- K5: top-20 per row (warp per row, vectorized loads) ----------------
// slot s (0..31) of a lane maps to global j = (s>>2)*128 + lane*4 + (s&3);
// ascending s == ascending j per lane, so tie-breaks match lax.top_k.
// All top-k state is statically-indexed registers (sorted top-3 cache + bitmask).
__global__ void __launch_bounds__(256) k_topk(){
  int warp = threadIdx.x >> 5, lane = threadIdx.x & 31;
  int row = blockIdx.x*8 + warp;
  const float4* srow = (const float4*)(g_scores + (size_t)row*NN);
  float v[32];
  #pragma unroll
  for (int c = 0; c < 8; c++){
    float4 q = srow[c*32 + lane];
    v[c*4+0] = q.x; v[c*4+1] = q.y; v[c*4+2] = q.z; v[c*4+3] = q.w;
  }
  float c0v = -CUDART_INF_F, c1v = -CUDART_INF_F, c2v = -CUDART_INF_F;
  int c0s = 0, c1s = 0, c2s = 0;
  #pragma unroll
  for (int s = 0; s < 32; s++){
    float x = v[s];
    if (x > c2v){
      if (x > c1v){
        c2v = c1v; c2s = c1s;
        if (x > c0v){ c1v = c0v; c1s = c0s; c0v = x; c0s = s; }
        else        { c1v = x; c1s = s; }
      } else { c2v = x; c2s = s; }
    }
  }
  unsigned used = 0u;
  int p = 0;
  int cs = c0s;
  float candv = c0v;
  int candg = ((c0s >> 2) << 7) + (lane << 2) + (c0s & 3);
  float* otv = g_tv + row*KK;
  int*   oti = g_ti + row*KK;
  for (int k = 0; k < KK; k++){
    float bv = candv; int bg = candg;
    #pragma unroll
    for (int off = 16; off > 0; off >>= 1){
      float ov = __shfl_xor_sync(0xffffffffu, bv, off);
      int   og = __shfl_xor_sync(0xffffffffu, bg, off);
      if (ov > bv || (ov == bv && og < bg)){ bv = ov; bg = og; }
    }
    if (lane == 0){ otv[k] = bv; oti[k] = bg; }
    if (bg == candg){
      used |= 1u << cs;
      p++;
      if (p == 1){ cs = c1s; candv = c1v; candg = ((c1s>>2)<<7) + (lane<<2) + (c1s&3); }
      else if (p == 2){ cs = c2s; candv = c2v; candg = ((c2s>>2)<<7) + (lane<<2) + (c2s&3); }
      else {
        candv = -CUDART_INF_F; cs = -1;
        #pragma unroll
        for (int s = 0; s < 32; s++){
          if (!((used >> s) & 1u)){
            float x = v[s];
            if (x > candv){ candv = x; cs = s; }
          }
        }
        candg = (cs >= 0) ? (((cs>>2)<<7) + (lane<<2) + (cs&3)) : ((1<<20) + lane);
      }
    }
  }
}

// ---------------- K6: GAT attention + aggregation ----------------
__global__ void __launch_bounds__(256) k_gat(const float* __restrict__ bgnn){
  __shared__ int   sidx[4][KK];
  __shared__ float stv[4][KK];
  __shared__ float sw[4][KK+1];
  int t = threadIdx.x;
  int g = t >> 6, d = t & 63;
  int row = blockIdx.x*4 + g;
  int b = row >> 10, i = row & (NN-1);
  if (d < KK){
    stv[g][d] = g_tv[row*KK + d];
    sidx[g][d] = g_ti[row*KK + d];
  }
  __syncthreads();
  if (d < 32){
    int lane = d;
    float si = g_si[row];
    float a;
    if (lane < KK){
      int j = sidx[g][lane];
      float sj = g_sj[b*NN + j];
      a = (j == i) ? -CUDART_INF_F : lrelu(si + sj);
    } else if (lane == KK){
      a = lrelu(si + g_sj[row]);
    } else a = -CUDART_INF_F;
    float m = a;
    #pragma unroll
    for (int off = 16; off > 0; off >>= 1) m = fmaxf(m, __shfl_xor_sync(0xffffffffu, m, off));
    float e = (lane <= KK) ? expf(a - m) : 0.f;
    float s = e;
    #pragma unroll
    for (int off = 16; off > 0; off >>= 1) s += __shfl_xor_sync(0xffffffffu, s, off);
    float att = e / s;
    float tvv = (lane < KK) ? stv[g][lane] : -CUDART_INF_F;
    float m2 = tvv;
    #pragma unroll
    for (int off = 16; off > 0; off >>= 1) m2 = fmaxf(m2, __shfl_xor_sync(0xffffffffu, m2, off));
    float e2 = (lane < KK) ? expf(tvv - m2) : 0.f;
    float s2 = e2;
    #pragma unroll
    for (int off = 16; off > 0; off >>= 1) s2 += __shfl_xor_sync(0xffffffffu, s2, off);
    if (lane <= KK)
      sw[g][lane] = (lane < KK) ? att * (e2 / s2) : att;
  }
  __syncthreads();
  // prefetch indices to registers, fully unroll gather -> high MLP
  int idx[KK];
  #pragma unroll
  for (int k = 0; k < KK; k++) idx[k] = sidx[g][k];
  const float* xb = g_xlin + (size_t)b*NN*DD;
  float acc = sw[g][KK] * g_xlin[row*DD + d];
  #pragma unroll
  for (int k = 0; k < KK; k++)
    acc = fmaf(sw[g][k], xb[(size_t)idx[k]*DD + d], acc);
  acc += bgnn[d];
  g_gnn[row*DD + d] = acc;
}

// ---------------- K7: BN1 stats ----------------
__global__ void __launch_bounds__(256) k_stats1(){
  __shared__ float ss[256], sq[256];
  int t = threadIdx.x;
  int c = t >> 6, d = t & 63;
  float s = 0.f, q = 0.f;
  int base = blockIdx.x * 256;
  for (int it = 0; it < 64; it++){
    int row = base + it*4 + c;
    float x = g_gnn[row*DD + d];
    s += x;
    q = fmaf(x, x, q);
  }
  ss[t] = s; sq[t] = q;
  __syncthreads();
  if (t < 64){
    double S = (double)ss[t] + ss[t+64] + ss[t+128] + ss[t+192];
    double Q = (double)sq[t] + sq[t+64] + sq[t+128] + sq[t+192];
    atomicAdd(&g_stats[d], S);
    atomicAdd(&g_stats[DD + d], Q);
  }
}

// ---------------- K8: BN2 stats from recomputed y ----------------
__global__ void __launch_bounds__(256) k_bn1mul(const float* __restrict__ g1,
    const float* __restrict__ be1, const float* __restrict__ net){
  __shared__ float ss[256], sq[256];
  int t = threadIdx.x;
  int c = t >> 6, d = t & 63;
  double inv = 1.0 / (double)NROWS;
  double mu = g_stats[d] * inv;
  double var = g_stats[DD + d] * inv - mu*mu;
  float scale = g1[d] * rsqrtf((float)var + BN_EPS);
  float shift = be1[d] - (float)mu * scale;
  float s = 0.f, q = 0.f;
  int base = blockIdx.x * 256;
  for (int it = 0; it < 64; it++){
    int row = base + it*4 + c;
    float x = g_gnn[row*DD + d];
    float gv = fmaxf(fmaf(x, scale, shift), 0.f);
    float y = gv * net[(row & (NN-1))*DD + d];
    s += y;
    q = fmaf(y, y, q);
  }
  ss[t] = s; sq[t] = q;
  __syncthreads();
  if (t < 64){
    double S = (double)ss[t] + ss[t+64] + ss[t+128] + ss[t+192];
    double Q = (double)sq[t] + sq[t+64] + sq[t+128] + sq[t+192];
    atomicAdd(&g_stats[2*DD + d], S);
    atomicAdd(&g_stats[3*DD + d], Q);
  }
}

// ---------------- K9: BN2 + relu + output head ----------------
__global__ void __launch_bounds__(256) k_head(const float* __restrict__ g1,
    const float* __restrict__ be1, const float* __restrict__ net,
    const float* __restrict__ g2, const float* __restrict__ be2,
    const float* __restrict__ Wo, const float* __restrict__ bo,
    float* __restrict__ dout){
  int warp = threadIdx.x >> 5;
  int lane = threadIdx.x & 31;
  int row = blockIdx.x*8 + warp;
  int n = row & (NN-1);
  double inv = 1.0 / (double)NROWS;
  float acc = 0.f;
  #pragma unroll
  for (int h = 0; h < 2; h++){
    int d = lane + h*32;
    double mu1 = g_stats[d] * inv;
    double var1 = g_stats[DD + d] * inv - mu1*mu1;
    float sc1 = g1[d] * rsqrtf((float)var1 + BN_EPS);
    float sh1 = be1[d] - (float)mu1 * sc1;
    double mu2 = g_stats[2*DD + d] * inv;
    double var2 = g_stats[3*DD + d] * inv - mu2*mu2;
    float sc2 = g2[d] * rsqrtf((float)var2 + BN_EPS);
    float sh2 = be2[d] - (float)mu2 * sc2;
    float x = g_gnn[row*DD + d];
    float gv = fmaxf(fmaf(x, sc1, sh1), 0.f);
    float y = gv * net[n*DD + d];
    float r = fmaxf(fmaf(y, sc2, sh2), 0.f);
    acc = fmaf(r, Wo[d], acc);
  }
  #pragma unroll
  for (int off = 16; off > 0; off >>= 1)
    acc += __shfl_down_sync(0xffffffffu, acc, off);
  if (lane == 0) dout[row] = acc + bo[0];
}

// ---------------- launch ----------------
extern "C" void kernel_launch(void* const* d_in, const int* in_sizes, int n_in,
                              void* d_out, int out_size) {
  const float* data   = (const float*)d_in[0];
  const float* gum    = (const float*)d_in[1];
  const float* Wc     = (const float*)d_in[2];
  const float* bc     = (const float*)d_in[3];
  const float* Wap    = (const float*)d_in[4];
  const float* bap    = (const float*)d_in[5];
  const float* Wav    = (const float*)d_in[6];
  const float* Wr     = (const float*)d_in[7];
  const float* br     = (const float*)d_in[8];
  const float* ebase  = (const float*)d_in[9];
  const float* lru    = (const float*)d_in[10];
  const float* lrv    = (const float*)d_in[11];
  const float* Wg     = (const float*)d_in[12];
  const float* ai     = (const float*)d_in[13];
  const float* aj     = (const float*)d_in[14];
  const float* aei    = (const float*)d_in[15];
  const float* aej    = (const float*)d_in[16];
  const float* bgnn   = (const float*)d_in[17];
  const float* g1     = (const float*)d_in[18];
  const float* be1    = (const float*)d_in[19];
  const float* net    = (const float*)d_in[20];
  const float* g2     = (const float*)d_in[21];
  const float* be2    = (const float*)d_in[22];
  const float* Wo     = (const float*)d_in[23];
  const float* bo     = (const float*)d_in[24];

  float* out    = (float*)d_out;              // [B,N]   32768
  float* hs_out = out + NROWS;                // [B,D]   2048
  float* ps_out = hs_out + BB*DD;             // [B,M]   128

  const int SC_SMEM = 2*64*132*4;             // 67584 B
  cudaFuncSetAttribute(k_scores, cudaFuncAttributeMaxDynamicSharedMemorySize, SC_SMEM);

  k_cond<<<NROWS/8, 256>>>(data, Wc, bc, Wap, bap, Wav, Wg, ebase, lru, lrv);
  k_hsys<<<dim3(HCHUNK, BB), 256>>>(Wr, br, gum, hs_out, ps_out);
  k_mixed<<<NROWS/8, 256>>>(ai, aj, aei, aej);
  k_scores<<<dim3(36, 1, BB), 256, SC_SMEM>>>();   // 4th launch -> ncu capture window
  k_topk<<<NROWS/8, 256>>>();
  k_gat<<<NROWS/4, 256>>>(bgnn);
  k_stats1<<<128, 256>>>();
  k_bn1mul<<<128, 256>>>(g1, be1, net);
  k_head<<<NROWS/8, 256>>>(g1, be1, net, g2, be2, Wo, bo, out);
}